// round 16
// baseline (speedup 1.0000x reference)
#include <cuda_runtime.h>
#include <math.h>
#include <stdint.h>

#define LQ 2048
#define DD 1024
#define NH 16
#define DHD 64

__device__ float g_h [LQ*DD];
__device__ float g_xr[LQ*DD];
__device__ float g_q [NH*LQ*DHD];
__device__ float g_k [NH*LQ*DHD];
__device__ float g_v [NH*LQ*DHD];
__device__ float g_o [LQ*DD];
__device__ float g_o2[LQ*DD];
__device__ float g_yo[LQ*DD];
__device__ float g_yo2[LQ*DD];
__device__ float g_gg[LQ*DD];
__device__ float g_wt[5*1024*1024];
__device__ float g_part[NH*LQ*16];
__device__ float g_sinv[NH*LQ];

__device__ __forceinline__ uint32_t f2tf(float f) {
    uint32_t u;
    asm("cvt.rna.tf32.f32 %0, %1;" : "=r"(u) : "f"(f));
    return u;
}
__device__ __forceinline__ float rnaf(float f) { return __uint_as_float(f2tf(f)); }

__device__ __forceinline__ void mma8(float* c,
                                     uint32_t a0, uint32_t a1, uint32_t a2, uint32_t a3,
                                     uint32_t b0, uint32_t b1) {
    asm volatile("mma.sync.aligned.m16n8k8.row.col.f32.tf32.tf32.f32 "
        "{%0,%1,%2,%3}, {%4,%5,%6,%7}, {%8,%9}, {%0,%1,%2,%3};"
        : "+f"(c[0]), "+f"(c[1]), "+f"(c[2]), "+f"(c[3])
        : "r"(a0), "r"(a1), "r"(a2), "r"(a3), "r"(b0), "r"(b1));
}

__device__ __forceinline__ uint32_t smem_u32(const void* p) {
    return (uint32_t)__cvta_generic_to_shared(p);
}
#define CP16(dst_u32, src_ptr) \
    asm volatile("cp.async.cg.shared.global [%0], [%1], 16;" :: "r"(dst_u32), "l"(src_ptr))
#define CP_COMMIT() asm volatile("cp.async.commit_group;")
#define CP_WAIT(n)  asm volatile("cp.async.wait_group %0;" :: "n"(n))

// triangular decode: bx -> (ti, tj) with tj <= ti
__device__ __forceinline__ void tri_decode(int bx, int& ti, int& tj) {
    int i = (int)((sqrtf(8.f*(float)bx + 1.f) - 1.f) * 0.5f);
    while ((i + 1)*(i + 2)/2 <= bx) i++;
    while (i*(i + 1)/2 > bx) i--;
    ti = i;
    tj = bx - i*(i + 1)/2;
}

// ---------------- LayerNorm (+tf32-rounded h and x copy) ----------------
__global__ void ln_kernel(const float* __restrict__ x,
                          const float* __restrict__ gamma,
                          const float* __restrict__ beta) {
    __shared__ float red[8];
    int row = blockIdx.x;
    int t = threadIdx.x;
    const float* xr = x + (size_t)row * DD;
    float v[4];
    float s = 0.f;
#pragma unroll
    for (int i = 0; i < 4; i++) { v[i] = xr[t + 256*i]; s += v[i]; }
#pragma unroll
    for (int o = 16; o; o >>= 1) s += __shfl_xor_sync(0xffffffffu, s, o);
    if ((t & 31) == 0) red[t >> 5] = s;
    __syncthreads();
    float tot = 0.f;
#pragma unroll
    for (int w = 0; w < 8; w++) tot += red[w];
    float mean = tot * (1.f / DD);
    __syncthreads();
    float s2 = 0.f;
#pragma unroll
    for (int i = 0; i < 4; i++) { float d = v[i] - mean; s2 += d*d; }
#pragma unroll
    for (int o = 16; o; o >>= 1) s2 += __shfl_xor_sync(0xffffffffu, s2, o);
    if ((t & 31) == 0) red[t >> 5] = s2;
    __syncthreads();
    float tot2 = 0.f;
#pragma unroll
    for (int w = 0; w < 8; w++) tot2 += red[w];
    float inv = rsqrtf(tot2 * (1.f / DD) + 1e-5f);
#pragma unroll
    for (int i = 0; i < 4; i++) {
        int c = t + 256*i;
        g_h [(size_t)row*DD + c] = rnaf((v[i] - mean) * inv * gamma[c] + beta[c]);
        g_xr[(size_t)row*DD + c] = rnaf(v[i]);
    }
}

// ---------------- weight tf32 rounding ----------------
__global__ void prep_w(const float* __restrict__ Wq, const float* __restrict__ Wk,
                       const float* __restrict__ Wv, const float* __restrict__ Wo,
                       const float* __restrict__ Wg) {
    int z = blockIdx.y;
    const float* W = (z == 0) ? Wq : (z == 1) ? Wk : (z == 2) ? Wv : (z == 3) ? Wo : Wg;
    float* dst = g_wt + (size_t)z * 1048576u;
    int idx = (blockIdx.x * 256 + threadIdx.x) * 4;
    float4 v = *(const float4*)&W[idx];
    v.x = rnaf(v.x); v.y = rnaf(v.y); v.z = rnaf(v.z); v.w = rnaf(v.w);
    *(float4*)&dst[idx] = v;
}

// ---------------- tf32 GEMM: 128x128 tile, kc=16, 3-stage cp.async ----------------
// mode 1 applies RoPE (first 16 head dims) + tf32 rounding in epilogue.
#define AST 20
#define BST 136
#define ATILE (128*AST)   // 2560 words
#define BTILE (16*BST)    // 2176 words
#define GEMM_SMEM_WORDS (3*(ATILE + BTILE))   // 14208 words = 56832 B

__device__ __forceinline__ void gemm_core(const float* __restrict__ A,
                                          const float* __restrict__ B,
                                          float* __restrict__ C, int mode,
                                          uint32_t* sA, uint32_t* sB,
                                          int kbeg, int nkt) {
    int t = threadIdx.x;
    int bm = blockIdx.y * 128, bn = blockIdx.x * 128;
    int lane = t & 31, wid = t >> 5;
    int g = lane >> 2, tg = lane & 3;
    int wm = (wid >> 2) * 64, wn = (wid & 3) * 32;

    int arow = t >> 1, ac0 = (t & 1) * 8;
    int brow = t & 15, bc0 = (t >> 4) * 8;
    const float* Abase = A + (size_t)(bm + arow)*1024 + kbeg + ac0;
    const float* Bbase = B + (size_t)(kbeg + brow)*1024 + bn + bc0;
    uint32_t sAa = smem_u32(sA) + (uint32_t)(arow*AST + ac0)*4;
    uint32_t sBa = smem_u32(sB) + (uint32_t)(brow*BST + bc0)*4;

    float acc[4][4][4];
#pragma unroll
    for (int i = 0; i < 4; i++)
#pragma unroll
        for (int j = 0; j < 4; j++)
#pragma unroll
            for (int q = 0; q < 4; q++) acc[i][j][q] = 0.f;

#define ISSUE(kt) {                                                      \
    int st_ = (kt) % 3; int k0_ = (kt) * 16;                             \
    CP16(sAa + st_*ATILE*4,      Abase + k0_);                           \
    CP16(sAa + st_*ATILE*4 + 16, Abase + k0_ + 4);                       \
    CP16(sBa + st_*BTILE*4,      Bbase + (size_t)k0_*1024);              \
    CP16(sBa + st_*BTILE*4 + 16, Bbase + (size_t)k0_*1024 + 4);          \
}

#define COMP(stg) {                                                      \
    const uint32_t* Ab = sA + (stg)*ATILE;                               \
    const uint32_t* Bb = sB + (stg)*BTILE;                               \
    _Pragma("unroll")                                                    \
    for (int ks = 0; ks < 2; ks++) {                                     \
        uint32_t af[4][4], bf[4][2];                                     \
        _Pragma("unroll")                                                \
        for (int mt = 0; mt < 4; mt++) {                                 \
            const uint32_t* pa = Ab + (wm + mt*16 + g)*AST + ks*8 + tg;  \
            af[mt][0] = pa[0];       af[mt][1] = pa[8*AST];              \
            af[mt][2] = pa[4];       af[mt][3] = pa[8*AST + 4];          \
        }                                                                \
        _Pragma("unroll")                                                \
        for (int nt = 0; nt < 4; nt++) {                                 \
            const uint32_t* pb = Bb + (ks*8 + tg)*BST + wn + nt*8 + g;   \
            bf[nt][0] = pb[0];       bf[nt][1] = pb[4*BST];              \
        }                                                                \
        _Pragma("unroll")                                                \
        for (int mt = 0; mt < 4; mt++)                                   \
            _Pragma("unroll")                                            \
            for (int nt = 0; nt < 4; nt++)                               \
                mma8(acc[mt][nt], af[mt][0], af[mt][1], af[mt][2],       \
                     af[mt][3], bf[nt][0], bf[nt][1]);                   \
    }                                                                    \
}

    ISSUE(0); CP_COMMIT();
    ISSUE(1); CP_COMMIT();
    for (int kt = 0; kt < nkt; kt++) {
        CP_WAIT(1);
        __syncthreads();
        if (kt + 2 < nkt) { ISSUE(kt + 2); }
        CP_COMMIT();
        COMP(kt % 3);
    }

    if (mode == 1 && (wn & 32) == 0) {
        // fused RoPE: d = nt*8 + 2tg + e; nt=0 (d<8) pairs with nt=1 (d+8)
#pragma unroll
        for (int mt = 0; mt < 4; mt++) {
#pragma unroll
            for (int rr = 0; rr < 2; rr++) {
                int l = bm + wm + mt*16 + g + rr*8;
#pragma unroll
                for (int e = 0; e < 2; e++) {
                    int p = 2*tg + e;
                    float invf = powf(10000.f, -(float)p * 0.125f);
                    float ang = (float)l * invf;
                    float s, c;
                    sincosf(ang, &s, &c);
                    float x1 = acc[mt][0][rr*2+e];
                    float x2 = acc[mt][1][rr*2+e];
                    acc[mt][0][rr*2+e] = x1*c - x2*s;
                    acc[mt][1][rr*2+e] = x2*c + x1*s;
                }
            }
        }
    }

#pragma unroll
    for (int mt = 0; mt < 4; mt++) {
#pragma unroll
        for (int nt = 0; nt < 4; nt++) {
            int m = bm + wm + mt*16 + g;
            int n = bn + wn + nt*8 + 2*tg;
            if (mode == 0) {
                float2 v0 = make_float2(acc[mt][nt][0], acc[mt][nt][1]);
                float2 v1 = make_float2(acc[mt][nt][2], acc[mt][nt][3]);
                *(float2*)&C[(size_t)m*1024 + n] = v0;
                *(float2*)&C[(size_t)(m+8)*1024 + n] = v1;
            } else {
                float2 v0 = make_float2(rnaf(acc[mt][nt][0]), rnaf(acc[mt][nt][1]));
                float2 v1 = make_float2(rnaf(acc[mt][nt][2]), rnaf(acc[mt][nt][3]));
                size_t b0i = ((size_t)(n >> 6)*LQ + m)*DHD + (n & 63);
                size_t b1i = ((size_t)(n >> 6)*LQ + m + 8)*DHD + (n & 63);
                *(float2*)&C[b0i] = v0;
                *(float2*)&C[b1i] = v1;
            }
        }
    }
#undef ISSUE
#undef COMP
}

// z=0..2: Wq/Wk/Wv head-major+RoPE; z=3: x@Wg plain
__global__ void __launch_bounds__(256, 2)
gemm_qkvg() {
    extern __shared__ uint32_t smg[];
    uint32_t* sA = smg;
    uint32_t* sB = smg + 3*ATILE;
    int z = blockIdx.z;
    if (z < 3) {
        const float* B = g_wt + (size_t)z * 1048576u;
        float* C = (z == 0) ? g_q : (z == 1) ? g_k : g_v;
        gemm_core(g_h, B, C, 1, sA, sB, 0, 64);
    } else {
        gemm_core(g_xr, g_wt + 4u*1048576u, g_gg, 0, sA, sB, 0, 64);
    }
}

// Wo GEMM split-K: z=0 -> K[0,512) into g_yo; z=1 -> K[512,1024) into g_yo2
__global__ void __launch_bounds__(256, 2)
gemm_o() {
    extern __shared__ uint32_t smg[];
    uint32_t* sA = smg;
    uint32_t* sB = smg + 3*ATILE;
    int z = blockIdx.z;
    float* C = (z == 0) ? g_yo : g_yo2;
    gemm_core(g_o, g_wt + 3u*1048576u, C, 0, sA, sB, z * 512, 32);
}

// ---------------- masked-region stream: dots = prev - 1e9, zero partials ----------------
__global__ void __launch_bounds__(256)
qk_masked(const float* __restrict__ prev, float* __restrict__ dots) {
    int m = blockIdx.x;                 // 0..119: tiles with tj > ti
    int h = blockIdx.y;
    int r;
    int i = (int)((sqrtf(8.f*(float)m + 1.f) - 1.f) * 0.5f);
    while ((i + 1)*(i + 2)/2 <= m) i++;
    while (i*(i + 1)/2 > m) i--;
    r = m - i*(i + 1)/2;                // ti = r, tj = i+1
    int i0 = r * 128, j0 = (i + 1) * 128;
    int t = threadIdx.x;

    int row = t >> 1;
    int c0 = (t & 1) * 64;
    size_t rowb = ((size_t)(h*LQ + i0 + row))*LQ + j0 + c0;
#pragma unroll
    for (int q = 0; q < 16; q++) {
        float4 pv = *(const float4*)&prev[rowb + q*4];
        float4 ov;
        ov.x = pv.x - 1000000000.0f;
        ov.y = pv.y - 1000000000.0f;
        ov.z = pv.z - 1000000000.0f;
        ov.w = pv.w - 1000000000.0f;
        *(float4*)&dots[rowb + q*4] = ov;
    }
    if (t < 128)
        g_part[((size_t)(h*LQ + i0 + t))*16 + (i + 1)] = 0.f;
}

// ---------------- QK live tiles: dots + per-row exp-sum partials ----------------
#define QST 68
#define QK_SMEM_WORDS (2*128*QST + 512)
__global__ void __launch_bounds__(256, 2)
qk_tf32(const float* __restrict__ prev, float* __restrict__ dots) {
    extern __shared__ uint32_t sm[];
    uint32_t* Qs = sm;                 // [128][68]
    uint32_t* Ks = sm + 128*QST;
    float* sparts = (float*)(sm + 2*128*QST);
    int t = threadIdx.x;
    int h = blockIdx.z;
    int ti, tj;
    tri_decode(blockIdx.x, ti, tj);
    int i0 = ti * 128, j0 = tj * 128;

    int lane = t & 31, wid = t >> 5;
    int g = lane >> 2, tg = lane & 3;
    int wm = (wid >> 2) * 64, wn = (wid & 3) * 32;

    const float* qh = g_q + (size_t)h*LQ*DHD;
    const float* kh = g_k + (size_t)h*LQ*DHD;

    {
        int m = t >> 1, cb = (t & 1) * 32;
        const float* qsrc = qh + (size_t)(i0 + m)*DHD + cb;
        const float* ksrc = kh + (size_t)(j0 + m)*DHD + cb;
        uint32_t qdst = smem_u32(Qs) + (uint32_t)(m*QST + cb)*4;
        uint32_t kdst = smem_u32(Ks) + (uint32_t)(m*QST + cb)*4;
#pragma unroll
        for (int q = 0; q < 8; q++) {
            CP16(qdst + q*16, qsrc + q*4);
            CP16(kdst + q*16, ksrc + q*4);
        }
        CP_COMMIT();
    }
    CP_WAIT(0);
    __syncthreads();

    float acc[4][4][4];
#pragma unroll
    for (int i = 0; i < 4; i++)
#pragma unroll
        for (int j = 0; j < 4; j++)
#pragma unroll
            for (int q = 0; q < 4; q++) acc[i][j][q] = 0.f;

#pragma unroll
    for (int ks = 0; ks < 8; ks++) {
        uint32_t af[4][4], bf[4][2];
#pragma unroll
        for (int mt = 0; mt < 4; mt++) {
            const uint32_t* pa = Qs + (wm + mt*16 + g)*QST + ks*8 + tg;
            af[mt][0] = pa[0];      af[mt][1] = pa[8*QST];
            af[mt][2] = pa[4];      af[mt][3] = pa[8*QST + 4];
        }
#pragma unroll
        for (int nt = 0; nt < 4; nt++) {
            const uint32_t* pb = Ks + (wn + nt*8 + g)*QST + ks*8 + tg;
            bf[nt][0] = pb[0];      bf[nt][1] = pb[4];
        }
#pragma unroll
        for (int mt = 0; mt < 4; mt++)
#pragma unroll
            for (int nt = 0; nt < 4; nt++)
                mma8(acc[mt][nt], af[mt][0], af[mt][1], af[mt][2], af[mt][3],
                     bf[nt][0], bf[nt][1]);
    }

    float slope = exp2f(-0.5f * (float)(h + 1));
    float s_t[4][2];
#pragma unroll
    for (int mt = 0; mt < 4; mt++) {
#pragma unroll
        for (int rr = 0; rr < 2; rr++) {
            int gi = i0 + wm + mt*16 + g + rr*8;
            size_t rowb = ((size_t)(h*LQ + gi))*LQ;
            float vals[8];
#pragma unroll
            for (int nt = 0; nt < 4; nt++) {
                int j = j0 + wn + nt*8 + 2*tg;
                float2 pv = *(const float2*)&prev[rowb + j];
                int rel0 = gi - j, rel1 = gi - (j + 1);
                float2 ov;
                ov.x = acc[mt][nt][rr*2+0]*0.125f + pv.x +
                       ((rel0 >= 0) ? (-slope*(float)rel0) : -1000000000.0f);
                ov.y = acc[mt][nt][rr*2+1]*0.125f + pv.y +
                       ((rel1 >= 0) ? (-slope*(float)rel1) : -1000000000.0f);
                *(float2*)&dots[rowb + j] = ov;
                vals[nt*2]   = ov.x;
                vals[nt*2+1] = ov.y;
            }
            float ssum = 0.f;
#pragma unroll
            for (int q = 0; q < 8; q++) ssum += __expf(vals[q]);
            s_t[mt][rr] = ssum;
        }
    }

#pragma unroll
    for (int mt = 0; mt < 4; mt++) {
#pragma unroll
        for (int rr = 0; rr < 2; rr++) {
            float s = s_t[mt][rr];
            s += __shfl_xor_sync(0xffffffffu, s, 1);
            s += __shfl_xor_sync(0xffffffffu, s, 2);
            if (tg == 0)
                sparts[(wid & 3)*128 + wm + mt*16 + g + rr*8] = s;
        }
    }
    __syncthreads();
    if (t < 128) {
        float S = sparts[t] + sparts[128 + t] + sparts[256 + t] + sparts[384 + t];
        g_part[((size_t)(h*LQ + i0 + t))*16 + tj] = S;
    }
}

// ---------------- row-sum finalize ----------------
__global__ void sumk_kernel() {
    int r = blockIdx.x * 256 + threadIdx.x;
    const float4* p = (const float4*)&g_part[(size_t)r * 16];
    float4 a = p[0], b = p[1], c = p[2], d = p[3];
    float s = a.x+a.y+a.z+a.w + b.x+b.y+b.z+b.w
            + c.x+c.y+c.z+c.w + d.x+d.y+d.z+d.w;
    g_sinv[r] = 1.f / s;
}

// ---------------- AV fused, split-K: 2 CTAs per (i-block, head) ----------------
#define PST 72
#define VSTRD 72
#define PS_WORDS (128*PST)
#define VS_WORDS (64*VSTRD)
#define AV_SMEM_WORDS (PS_WORDS + 2*VS_WORDS)
__global__ void __launch_bounds__(256, 2)
av_fused(const float* __restrict__ dots, float* __restrict__ attn) {
    extern __shared__ uint32_t sm2[];
    uint32_t* Ps = sm2;                 // [128][72]
    uint32_t* Vs = sm2 + PS_WORDS;      // [2][64][72]
    int t = threadIdx.x;
    int h = blockIdx.y;
    int bx = blockIdx.x;
    int tile = bx >> 1, split = bx & 1;
    int i0 = (15 - tile) * 128;          // heavy i-blocks get lowest bx
    int lane = t & 31, wid = t >> 5;
    int g = lane >> 2, tg = lane & 3;
    int wm2 = wid * 16;

    int nlive = i0/64 + 2;
    int half = (nlive + 1) >> 1;
    int cbeg = split ? half : 0;
    int cend = split ? nlive : half;
    float* obuf = split ? g_o2 : g_o;

    const float* vh = g_v + (size_t)h*LQ*DHD;
    int prow = t >> 1, pc0 = (t & 1) * 32;
    int vrow = t >> 2, vcb = (t & 3) * 16;
    float Si = g_sinv[h*LQ + i0 + prow];
    size_t rowbase = ((size_t)(h*LQ + i0 + prow))*LQ + pc0;

    uint32_t vdst = smem_u32(Vs) + (uint32_t)(vrow*VSTRD + vcb)*4;

    float oacc[8][4];
#pragma unroll
    for (int i = 0; i < 8; i++)
#pragma unroll
        for (int q = 0; q < 4; q++) oacc[i][q] = 0.f;

    float4 dbuf[8];
    {
        const float* dp = &dots[rowbase + (size_t)cbeg*64];
#pragma unroll
        for (int q = 0; q < 8; q++) dbuf[q] = *(const float4*)(dp + q*4);
        const float* vsrc = vh + (size_t)(cbeg*64 + vrow)*DHD + vcb;
#pragma unroll
        for (int q = 0; q < 4; q++)
            CP16(vdst + ((cbeg & 1) ? VS_WORDS*4 : 0) + q*16, vsrc + q*4);
        CP_COMMIT();
    }

    for (int c = cbeg; c < cend; c++) {
        int jc = c * 64;
        if (c + 1 < cend) {
            const float* vsrc = vh + (size_t)(jc + 64 + vrow)*DHD + vcb;
            uint32_t vd = vdst + ((c + 1) & 1) * VS_WORDS * 4;
#pragma unroll
            for (int q = 0; q < 4; q++)
                CP16(vd + q*16, vsrc + q*4);
        }
        CP_COMMIT();

#pragma unroll
        for (int q = 0; q < 8; q++) {
            float4 dv = dbuf[q];
            float4 p;
            p.x = __expf(dv.x) * Si;
            p.y = __expf(dv.y) * Si;
            p.z = __expf(dv.z) * Si;
            p.w = __expf(dv.w) * Si;
            *(float4*)&attn[rowbase + jc + q*4] = p;
            uint4 pu;
            pu.x = f2tf(p.x); pu.y = f2tf(p.y); pu.z = f2tf(p.z); pu.w = f2tf(p.w);
            *(uint4*)&Ps[prow*PST + pc0 + q*4] = pu;
        }
        if (c + 1 < cend) {
            const float* dp = &dots[rowbase + jc + 64];
#pragma unroll
            for (int q = 0; q < 8; q++) dbuf[q] = *(const float4*)(dp + q*4);
        }
        if (c + 1 < cend) { CP_WAIT(1); } else { CP_WAIT(0); }
        __syncthreads();

        const uint32_t* Vb = Vs + (c & 1) * VS_WORDS;
#pragma unroll
        for (int ks = 0; ks < 8; ks++) {
            const uint32_t* pa = Ps + (wm2 + g)*PST + ks*8 + tg;
            uint32_t a0 = pa[0], a1 = pa[8*PST], a2 = pa[4], a3 = pa[8*PST + 4];
#pragma unroll
            for (int nt = 0; nt < 8; nt++) {
                const uint32_t* pb = Vb + (ks*8 + tg)*VSTRD + nt*8 + g;
                mma8(oacc[nt], a0, a1, a2, a3, pb[0], pb[4*VSTRD]);
            }
        }
        __syncthreads();
    }

    // masked region zeros: split 1 handles it
    if (split) {
        float4 z = make_float4(0.f, 0.f, 0.f, 0.f);
        for (int jc = nlive*64; jc < LQ; jc += 64) {
#pragma unroll
            for (int q = 0; q < 8; q++)
                *(float4*)&attn[rowbase + jc + q*4] = z;
        }
    }

#pragma unroll
    for (int nt = 0; nt < 8; nt++) {
        int d = nt*8 + 2*tg;
        int i = i0 + wm2 + g;
        *(float2*)&obuf[(size_t)i*DD + h*DHD + d] =
            make_float2(oacc[nt][0], oacc[nt][1]);
        *(float2*)&obuf[(size_t)(i+8)*DD + h*DHD + d] =
            make_float2(oacc[nt][2], oacc[nt][3]);
    }
}

// ---------------- partial-o sum (+ tf32 round for the Wo GEMM) ----------------
__global__ void oadd_kernel() {
    int idx = (blockIdx.x * 256 + threadIdx.x) * 4;
    float4 a = *(const float4*)&g_o[idx];
    float4 b = *(const float4*)&g_o2[idx];
    a.x = rnaf(a.x + b.x); a.y = rnaf(a.y + b.y);
    a.z = rnaf(a.z + b.z); a.w = rnaf(a.w + b.w);
    *(float4*)&g_o[idx] = a;
}

// ---------------- final: y = sigmoid(x@Wg+bg) * (yo1+yo2+bo) + x ----------------
__global__ void final_kernel(const float* __restrict__ x,
                             const float* __restrict__ bo,
                             const float* __restrict__ bg,
                             float* __restrict__ y) {
    int idx = blockIdx.x * 256 + threadIdx.x;
    int n = idx & (DD - 1);
    float yo = g_yo[idx] + g_yo2[idx] + bo[n];
    float gg = g_gg[idx] + bg[n];
    float gate = 1.f / (1.f + __expf(-gg));
    y[idx] = gate * yo + x[idx];
}

extern "C" void kernel_launch(void* const* d_in, const int* in_sizes, int n_in,
                              void* d_out, int out_size) {
    const float* x     = (const float*)d_in[0];
    const float* prev  = (const float*)d_in[1];
    const float* Wq    = (const float*)d_in[2];
    const float* Wk    = (const float*)d_in[3];
    const float* Wv    = (const float*)d_in[4];
    const float* Wo    = (const float*)d_in[5];
    const float* bo    = (const float*)d_in[6];
    const float* gamma = (const float*)d_in[7];
    const float* beta  = (const float*)d_in[8];
    const float* Wg    = (const float*)d_in[9];
    const float* bg    = (const float*)d_in[10];

    float* y    = (float*)d_out;
    float* attn = y + (size_t)LQ * DD;
    float* dots = attn + (size_t)NH * LQ * LQ;

    size_t gsmb = (size_t)GEMM_SMEM_WORDS * 4;
    cudaFuncSetAttribute(gemm_qkvg, cudaFuncAttributeMaxDynamicSharedMemorySize, (int)gsmb);
    cudaFuncSetAttribute(gemm_o,    cudaFuncAttributeMaxDynamicSharedMemorySize, (int)gsmb);
    size_t qsmb = (size_t)QK_SMEM_WORDS * 4;
    cudaFuncSetAttribute(qk_tf32, cudaFuncAttributeMaxDynamicSharedMemorySize, (int)qsmb);
    size_t avsmb = (size_t)AV_SMEM_WORDS * 4;
    cudaFuncSetAttribute(av_fused, cudaFuncAttributeMaxDynamicSharedMemorySize, (int)avsmb);

    prep_w<<<dim3(1024, 5), 256>>>(Wq, Wk, Wv, Wo, Wg);
    ln_kernel<<<LQ, 256>>>(x, gamma, beta);

    gemm_qkvg<<<dim3(8, 16, 4), 256, gsmb>>>();

    qk_masked<<<dim3(120, 16), 256>>>(prev, dots);
    qk_tf32<<<dim3(136, 1, 16), 256, qsmb>>>(prev, dots);
    sumk_kernel<<<(NH*LQ)/256, 256>>>();
    av_fused<<<dim3(32, 16), 256, avsmb>>>(dots, attn);
    oadd_kernel<<<(LQ*DD)/1024, 256>>>();

    gemm_o<<<dim3(8, 16, 2), 256, gsmb>>>();

    final_kernel<<<(LQ*DD)/256, 256>>>(x, bo, bg, y);
}

// round 17
// speedup vs baseline: 1.0990x; 1.0990x over previous
#include <cuda_runtime.h>
#include <math.h>
#include <stdint.h>

#define LQ 2048
#define DD 1024
#define NH 16
#define DHD 64

__device__ float g_h [LQ*DD];
__device__ float g_xr[LQ*DD];
__device__ float g_q [NH*LQ*DHD];
__device__ float g_k [NH*LQ*DHD];
__device__ float g_v [NH*LQ*DHD];
__device__ float g_o [LQ*DD];
__device__ float g_o2[LQ*DD];
__device__ float g_yo[LQ*DD];
__device__ float g_yo2[LQ*DD];
__device__ float g_gg[LQ*DD];
__device__ float g_wt[5*1024*1024];
__device__ float g_part[NH*LQ*16];
__device__ float g_sinv[NH*LQ];

__device__ __forceinline__ uint32_t f2tf(float f) {
    uint32_t u;
    asm("cvt.rna.tf32.f32 %0, %1;" : "=r"(u) : "f"(f));
    return u;
}
__device__ __forceinline__ float rnaf(float f) { return __uint_as_float(f2tf(f)); }

__device__ __forceinline__ void mma8(float* c,
                                     uint32_t a0, uint32_t a1, uint32_t a2, uint32_t a3,
                                     uint32_t b0, uint32_t b1) {
    asm volatile("mma.sync.aligned.m16n8k8.row.col.f32.tf32.tf32.f32 "
        "{%0,%1,%2,%3}, {%4,%5,%6,%7}, {%8,%9}, {%0,%1,%2,%3};"
        : "+f"(c[0]), "+f"(c[1]), "+f"(c[2]), "+f"(c[3])
        : "r"(a0), "r"(a1), "r"(a2), "r"(a3), "r"(b0), "r"(b1));
}

__device__ __forceinline__ uint32_t smem_u32(const void* p) {
    return (uint32_t)__cvta_generic_to_shared(p);
}
#define CP16(dst_u32, src_ptr) \
    asm volatile("cp.async.cg.shared.global [%0], [%1], 16;" :: "r"(dst_u32), "l"(src_ptr))
#define CP_COMMIT() asm volatile("cp.async.commit_group;")
#define CP_WAIT(n)  asm volatile("cp.async.wait_group %0;" :: "n"(n))

// triangular decode: bx -> (ti, tj) with tj <= ti
__device__ __forceinline__ void tri_decode(int bx, int& ti, int& tj) {
    int i = (int)((sqrtf(8.f*(float)bx + 1.f) - 1.f) * 0.5f);
    while ((i + 1)*(i + 2)/2 <= bx) i++;
    while (i*(i + 1)/2 > bx) i--;
    ti = i;
    tj = bx - i*(i + 1)/2;
}

// ---------------- LayerNorm (+tf32-rounded h and x copy) ----------------
__global__ void ln_kernel(const float* __restrict__ x,
                          const float* __restrict__ gamma,
                          const float* __restrict__ beta) {
    __shared__ float red[8];
    int row = blockIdx.x;
    int t = threadIdx.x;
    const float* xr = x + (size_t)row * DD;
    float v[4];
    float s = 0.f;
#pragma unroll
    for (int i = 0; i < 4; i++) { v[i] = xr[t + 256*i]; s += v[i]; }
#pragma unroll
    for (int o = 16; o; o >>= 1) s += __shfl_xor_sync(0xffffffffu, s, o);
    if ((t & 31) == 0) red[t >> 5] = s;
    __syncthreads();
    float tot = 0.f;
#pragma unroll
    for (int w = 0; w < 8; w++) tot += red[w];
    float mean = tot * (1.f / DD);
    __syncthreads();
    float s2 = 0.f;
#pragma unroll
    for (int i = 0; i < 4; i++) { float d = v[i] - mean; s2 += d*d; }
#pragma unroll
    for (int o = 16; o; o >>= 1) s2 += __shfl_xor_sync(0xffffffffu, s2, o);
    if ((t & 31) == 0) red[t >> 5] = s2;
    __syncthreads();
    float tot2 = 0.f;
#pragma unroll
    for (int w = 0; w < 8; w++) tot2 += red[w];
    float inv = rsqrtf(tot2 * (1.f / DD) + 1e-5f);
#pragma unroll
    for (int i = 0; i < 4; i++) {
        int c = t + 256*i;
        g_h [(size_t)row*DD + c] = rnaf((v[i] - mean) * inv * gamma[c] + beta[c]);
        g_xr[(size_t)row*DD + c] = rnaf(v[i]);
    }
}

// ---------------- weight tf32 rounding ----------------
__global__ void prep_w(const float* __restrict__ Wq, const float* __restrict__ Wk,
                       const float* __restrict__ Wv, const float* __restrict__ Wo,
                       const float* __restrict__ Wg) {
    int z = blockIdx.y;
    const float* W = (z == 0) ? Wq : (z == 1) ? Wk : (z == 2) ? Wv : (z == 3) ? Wo : Wg;
    float* dst = g_wt + (size_t)z * 1048576u;
    int idx = (blockIdx.x * 256 + threadIdx.x) * 4;
    float4 v = *(const float4*)&W[idx];
    v.x = rnaf(v.x); v.y = rnaf(v.y); v.z = rnaf(v.z); v.w = rnaf(v.w);
    *(float4*)&dst[idx] = v;
}

// ---------------- tf32 GEMM: 128x128 tile, kc=16, 3-stage cp.async ----------------
// mode 1 applies RoPE (first 16 head dims) + tf32 rounding in epilogue.
#define AST 20
#define BST 136
#define ATILE (128*AST)   // 2560 words
#define BTILE (16*BST)    // 2176 words
#define GEMM_SMEM_WORDS (3*(ATILE + BTILE))   // 14208 words = 56832 B

__device__ __forceinline__ void gemm_core(const float* __restrict__ A,
                                          const float* __restrict__ B,
                                          float* __restrict__ C, int mode,
                                          uint32_t* sA, uint32_t* sB,
                                          int kbeg, int nkt) {
    int t = threadIdx.x;
    int bm = blockIdx.y * 128, bn = blockIdx.x * 128;
    int lane = t & 31, wid = t >> 5;
    int g = lane >> 2, tg = lane & 3;
    int wm = (wid >> 2) * 64, wn = (wid & 3) * 32;

    int arow = t >> 1, ac0 = (t & 1) * 8;
    int brow = t & 15, bc0 = (t >> 4) * 8;
    const float* Abase = A + (size_t)(bm + arow)*1024 + kbeg + ac0;
    const float* Bbase = B + (size_t)(kbeg + brow)*1024 + bn + bc0;
    uint32_t sAa = smem_u32(sA) + (uint32_t)(arow*AST + ac0)*4;
    uint32_t sBa = smem_u32(sB) + (uint32_t)(brow*BST + bc0)*4;

    float acc[4][4][4];
#pragma unroll
    for (int i = 0; i < 4; i++)
#pragma unroll
        for (int j = 0; j < 4; j++)
#pragma unroll
            for (int q = 0; q < 4; q++) acc[i][j][q] = 0.f;

#define ISSUE(kt) {                                                      \
    int st_ = (kt) % 3; int k0_ = (kt) * 16;                             \
    CP16(sAa + st_*ATILE*4,      Abase + k0_);                           \
    CP16(sAa + st_*ATILE*4 + 16, Abase + k0_ + 4);                       \
    CP16(sBa + st_*BTILE*4,      Bbase + (size_t)k0_*1024);              \
    CP16(sBa + st_*BTILE*4 + 16, Bbase + (size_t)k0_*1024 + 4);          \
}

#define COMP(stg) {                                                      \
    const uint32_t* Ab = sA + (stg)*ATILE;                               \
    const uint32_t* Bb = sB + (stg)*BTILE;                               \
    _Pragma("unroll")                                                    \
    for (int ks = 0; ks < 2; ks++) {                                     \
        uint32_t af[4][4], bf[4][2];                                     \
        _Pragma("unroll")                                                \
        for (int mt = 0; mt < 4; mt++) {                                 \
            const uint32_t* pa = Ab + (wm + mt*16 + g)*AST + ks*8 + tg;  \
            af[mt][0] = pa[0];       af[mt][1] = pa[8*AST];              \
            af[mt][2] = pa[4];       af[mt][3] = pa[8*AST + 4];          \
        }                                                                \
        _Pragma("unroll")                                                \
        for (int nt = 0; nt < 4; nt++) {                                 \
            const uint32_t* pb = Bb + (ks*8 + tg)*BST + wn + nt*8 + g;   \
            bf[nt][0] = pb[0];       bf[nt][1] = pb[4*BST];              \
        }                                                                \
        _Pragma("unroll")                                                \
        for (int mt = 0; mt < 4; mt++)                                   \
            _Pragma("unroll")                                            \
            for (int nt = 0; nt < 4; nt++)                               \
                mma8(acc[mt][nt], af[mt][0], af[mt][1], af[mt][2],       \
                     af[mt][3], bf[nt][0], bf[nt][1]);                   \
    }                                                                    \
}

    ISSUE(0); CP_COMMIT();
    ISSUE(1); CP_COMMIT();
    for (int kt = 0; kt < nkt; kt++) {
        CP_WAIT(1);
        __syncthreads();
        if (kt + 2 < nkt) { ISSUE(kt + 2); }
        CP_COMMIT();
        COMP(kt % 3);
    }

    if (mode == 1 && (wn & 32) == 0) {
        // fused RoPE: d = nt*8 + 2tg + e; nt=0 (d<8) pairs with nt=1 (d+8)
#pragma unroll
        for (int mt = 0; mt < 4; mt++) {
#pragma unroll
            for (int rr = 0; rr < 2; rr++) {
                int l = bm + wm + mt*16 + g + rr*8;
#pragma unroll
                for (int e = 0; e < 2; e++) {
                    int p = 2*tg + e;
                    float invf = powf(10000.f, -(float)p * 0.125f);
                    float ang = (float)l * invf;
                    float s, c;
                    sincosf(ang, &s, &c);
                    float x1 = acc[mt][0][rr*2+e];
                    float x2 = acc[mt][1][rr*2+e];
                    acc[mt][0][rr*2+e] = x1*c - x2*s;
                    acc[mt][1][rr*2+e] = x2*c + x1*s;
                }
            }
        }
    }

#pragma unroll
    for (int mt = 0; mt < 4; mt++) {
#pragma unroll
        for (int nt = 0; nt < 4; nt++) {
            int m = bm + wm + mt*16 + g;
            int n = bn + wn + nt*8 + 2*tg;
            if (mode == 0) {
                float2 v0 = make_float2(acc[mt][nt][0], acc[mt][nt][1]);
                float2 v1 = make_float2(acc[mt][nt][2], acc[mt][nt][3]);
                *(float2*)&C[(size_t)m*1024 + n] = v0;
                *(float2*)&C[(size_t)(m+8)*1024 + n] = v1;
            } else {
                float2 v0 = make_float2(rnaf(acc[mt][nt][0]), rnaf(acc[mt][nt][1]));
                float2 v1 = make_float2(rnaf(acc[mt][nt][2]), rnaf(acc[mt][nt][3]));
                size_t b0i = ((size_t)(n >> 6)*LQ + m)*DHD + (n & 63);
                size_t b1i = ((size_t)(n >> 6)*LQ + m + 8)*DHD + (n & 63);
                *(float2*)&C[b0i] = v0;
                *(float2*)&C[b1i] = v1;
            }
        }
    }
#undef ISSUE
#undef COMP
}

// z=0..2: Wq/Wk/Wv head-major+RoPE; z=3: x@Wg plain
__global__ void __launch_bounds__(256, 2)
gemm_qkvg() {
    extern __shared__ uint32_t smg[];
    uint32_t* sA = smg;
    uint32_t* sB = smg + 3*ATILE;
    int z = blockIdx.z;
    if (z < 3) {
        const float* B = g_wt + (size_t)z * 1048576u;
        float* C = (z == 0) ? g_q : (z == 1) ? g_k : g_v;
        gemm_core(g_h, B, C, 1, sA, sB, 0, 64);
    } else {
        gemm_core(g_xr, g_wt + 4u*1048576u, g_gg, 0, sA, sB, 0, 64);
    }
}

// Wo GEMM split-K: z=0 -> K[0,512) into g_yo; z=1 -> K[512,1024) into g_yo2
__global__ void __launch_bounds__(256, 2)
gemm_o() {
    extern __shared__ uint32_t smg[];
    uint32_t* sA = smg;
    uint32_t* sB = smg + 3*ATILE;
    int z = blockIdx.z;
    float* C = (z == 0) ? g_yo : g_yo2;
    gemm_core(g_o, g_wt + 3u*1048576u, C, 0, sA, sB, z * 512, 32);
}

// ---------------- masked-region stream: dots = prev - 1e9, zero partials ----------------
// Coalesced: one warp covers one 128-float row per iteration (lane l -> col 4l).
__global__ void __launch_bounds__(256)
qk_masked(const float* __restrict__ prev, float* __restrict__ dots) {
    int m = blockIdx.x;                 // 0..119: tiles with tj > ti
    int h = blockIdx.y;
    int i = (int)((sqrtf(8.f*(float)m + 1.f) - 1.f) * 0.5f);
    while ((i + 1)*(i + 2)/2 <= m) i++;
    while (i*(i + 1)/2 > m) i--;
    int r = m - i*(i + 1)/2;            // ti = r, tj = i+1
    int i0 = r * 128, j0 = (i + 1) * 128;
    int t = threadIdx.x;
    int lane = t & 31, wid = t >> 5;

    size_t base = ((size_t)(h*LQ + i0))*LQ + j0 + lane*4;
#pragma unroll
    for (int it = 0; it < 16; it++) {
        int row = wid + it*8;
        size_t off = base + (size_t)row*LQ;
        float4 pv = *(const float4*)&prev[off];
        float4 ov;
        ov.x = pv.x - 1000000000.0f;
        ov.y = pv.y - 1000000000.0f;
        ov.z = pv.z - 1000000000.0f;
        ov.w = pv.w - 1000000000.0f;
        *(float4*)&dots[off] = ov;
    }
    if (t < 128)
        g_part[((size_t)(h*LQ + i0 + t))*16 + (i + 1)] = 0.f;
}

// ---------------- QK live tiles: dots + per-row exp-sum partials ----------------
#define QST 68
#define QK_SMEM_WORDS (2*128*QST + 512)
__global__ void __launch_bounds__(256, 2)
qk_tf32(const float* __restrict__ prev, float* __restrict__ dots) {
    extern __shared__ uint32_t sm[];
    uint32_t* Qs = sm;                 // [128][68]
    uint32_t* Ks = sm + 128*QST;
    float* sparts = (float*)(sm + 2*128*QST);
    int t = threadIdx.x;
    int h = blockIdx.z;
    int ti, tj;
    tri_decode(blockIdx.x, ti, tj);
    int i0 = ti * 128, j0 = tj * 128;

    int lane = t & 31, wid = t >> 5;
    int g = lane >> 2, tg = lane & 3;
    int wm = (wid >> 2) * 64, wn = (wid & 3) * 32;

    const float* qh = g_q + (size_t)h*LQ*DHD;
    const float* kh = g_k + (size_t)h*LQ*DHD;

    {
        int m = t >> 1, cb = (t & 1) * 32;
        const float* qsrc = qh + (size_t)(i0 + m)*DHD + cb;
        const float* ksrc = kh + (size_t)(j0 + m)*DHD + cb;
        uint32_t qdst = smem_u32(Qs) + (uint32_t)(m*QST + cb)*4;
        uint32_t kdst = smem_u32(Ks) + (uint32_t)(m*QST + cb)*4;
#pragma unroll
        for (int q = 0; q < 8; q++) {
            CP16(qdst + q*16, qsrc + q*4);
            CP16(kdst + q*16, ksrc + q*4);
        }
        CP_COMMIT();
    }
    CP_WAIT(0);
    __syncthreads();

    float acc[4][4][4];
#pragma unroll
    for (int i = 0; i < 4; i++)
#pragma unroll
        for (int j = 0; j < 4; j++)
#pragma unroll
            for (int q = 0; q < 4; q++) acc[i][j][q] = 0.f;

#pragma unroll
    for (int ks = 0; ks < 8; ks++) {
        uint32_t af[4][4], bf[4][2];
#pragma unroll
        for (int mt = 0; mt < 4; mt++) {
            const uint32_t* pa = Qs + (wm + mt*16 + g)*QST + ks*8 + tg;
            af[mt][0] = pa[0];      af[mt][1] = pa[8*QST];
            af[mt][2] = pa[4];      af[mt][3] = pa[8*QST + 4];
        }
#pragma unroll
        for (int nt = 0; nt < 4; nt++) {
            const uint32_t* pb = Ks + (wn + nt*8 + g)*QST + ks*8 + tg;
            bf[nt][0] = pb[0];      bf[nt][1] = pb[4];
        }
#pragma unroll
        for (int mt = 0; mt < 4; mt++)
#pragma unroll
            for (int nt = 0; nt < 4; nt++)
                mma8(acc[mt][nt], af[mt][0], af[mt][1], af[mt][2], af[mt][3],
                     bf[nt][0], bf[nt][1]);
    }

    float slope = exp2f(-0.5f * (float)(h + 1));
    float s_t[4][2];
#pragma unroll
    for (int mt = 0; mt < 4; mt++) {
#pragma unroll
        for (int rr = 0; rr < 2; rr++) {
            int gi = i0 + wm + mt*16 + g + rr*8;
            size_t rowb = ((size_t)(h*LQ + gi))*LQ;
            float vals[8];
#pragma unroll
            for (int nt = 0; nt < 4; nt++) {
                int j = j0 + wn + nt*8 + 2*tg;
                float2 pv = *(const float2*)&prev[rowb + j];
                int rel0 = gi - j, rel1 = gi - (j + 1);
                float2 ov;
                ov.x = acc[mt][nt][rr*2+0]*0.125f + pv.x +
                       ((rel0 >= 0) ? (-slope*(float)rel0) : -1000000000.0f);
                ov.y = acc[mt][nt][rr*2+1]*0.125f + pv.y +
                       ((rel1 >= 0) ? (-slope*(float)rel1) : -1000000000.0f);
                *(float2*)&dots[rowb + j] = ov;
                vals[nt*2]   = ov.x;
                vals[nt*2+1] = ov.y;
            }
            float ssum = 0.f;
#pragma unroll
            for (int q = 0; q < 8; q++) ssum += __expf(vals[q]);
            s_t[mt][rr] = ssum;
        }
    }

#pragma unroll
    for (int mt = 0; mt < 4; mt++) {
#pragma unroll
        for (int rr = 0; rr < 2; rr++) {
            float s = s_t[mt][rr];
            s += __shfl_xor_sync(0xffffffffu, s, 1);
            s += __shfl_xor_sync(0xffffffffu, s, 2);
            if (tg == 0)
                sparts[(wid & 3)*128 + wm + mt*16 + g + rr*8] = s;
        }
    }
    __syncthreads();
    if (t < 128) {
        float S = sparts[t] + sparts[128 + t] + sparts[256 + t] + sparts[384 + t];
        g_part[((size_t)(h*LQ + i0 + t))*16 + tj] = S;
    }
}

// ---------------- row-sum finalize ----------------
__global__ void sumk_kernel() {
    int r = blockIdx.x * 256 + threadIdx.x;
    const float4* p = (const float4*)&g_part[(size_t)r * 16];
    float4 a = p[0], b = p[1], c = p[2], d = p[3];
    float s = a.x+a.y+a.z+a.w + b.x+b.y+b.z+b.w
            + c.x+c.y+c.z+c.w + d.x+d.y+d.z+d.w;
    g_sinv[r] = 1.f / s;
}

// ---------------- AV fused, split-K: 2 CTAs per (i-block, head) ----------------
#define PST 72
#define VSTRD 72
#define PS_WORDS (128*PST)
#define VS_WORDS (64*VSTRD)
#define AV_SMEM_WORDS (PS_WORDS + 2*VS_WORDS)
__global__ void __launch_bounds__(256, 2)
av_fused(const float* __restrict__ dots, float* __restrict__ attn) {
    extern __shared__ uint32_t sm2[];
    uint32_t* Ps = sm2;                 // [128][72]
    uint32_t* Vs = sm2 + PS_WORDS;      // [2][64][72]
    int t = threadIdx.x;
    int h = blockIdx.y;
    int bx = blockIdx.x;
    int tile = bx >> 1, split = bx & 1;
    int i0 = (15 - tile) * 128;          // heavy i-blocks get lowest bx
    int lane = t & 31, wid = t >> 5;
    int g = lane >> 2, tg = lane & 3;
    int wm2 = wid * 16;

    int nlive = i0/64 + 2;
    int half = (nlive + 1) >> 1;
    int cbeg = split ? half : 0;
    int cend = split ? nlive : half;
    float* obuf = split ? g_o2 : g_o;

    const float* vh = g_v + (size_t)h*LQ*DHD;
    int prow = t >> 1, pc0 = (t & 1) * 32;
    int vrow = t >> 2, vcb = (t & 3) * 16;
    float Si = g_sinv[h*LQ + i0 + prow];
    size_t rowbase = ((size_t)(h*LQ + i0 + prow))*LQ + pc0;

    uint32_t vdst = smem_u32(Vs) + (uint32_t)(vrow*VSTRD + vcb)*4;

    float oacc[8][4];
#pragma unroll
    for (int i = 0; i < 8; i++)
#pragma unroll
        for (int q = 0; q < 4; q++) oacc[i][q] = 0.f;

    float4 dbuf[8];
    {
        const float* dp = &dots[rowbase + (size_t)cbeg*64];
#pragma unroll
        for (int q = 0; q < 8; q++) dbuf[q] = *(const float4*)(dp + q*4);
        const float* vsrc = vh + (size_t)(cbeg*64 + vrow)*DHD + vcb;
#pragma unroll
        for (int q = 0; q < 4; q++)
            CP16(vdst + ((cbeg & 1) ? VS_WORDS*4 : 0) + q*16, vsrc + q*4);
        CP_COMMIT();
    }

    for (int c = cbeg; c < cend; c++) {
        int jc = c * 64;
        if (c + 1 < cend) {
            const float* vsrc = vh + (size_t)(jc + 64 + vrow)*DHD + vcb;
            uint32_t vd = vdst + ((c + 1) & 1) * VS_WORDS * 4;
#pragma unroll
            for (int q = 0; q < 4; q++)
                CP16(vd + q*16, vsrc + q*4);
        }
        CP_COMMIT();

#pragma unroll
        for (int q = 0; q < 8; q++) {
            float4 dv = dbuf[q];
            float4 p;
            p.x = __expf(dv.x) * Si;
            p.y = __expf(dv.y) * Si;
            p.z = __expf(dv.z) * Si;
            p.w = __expf(dv.w) * Si;
            *(float4*)&attn[rowbase + jc + q*4] = p;
            uint4 pu;
            pu.x = f2tf(p.x); pu.y = f2tf(p.y); pu.z = f2tf(p.z); pu.w = f2tf(p.w);
            *(uint4*)&Ps[prow*PST + pc0 + q*4] = pu;
        }
        if (c + 1 < cend) {
            const float* dp = &dots[rowbase + jc + 64];
#pragma unroll
            for (int q = 0; q < 8; q++) dbuf[q] = *(const float4*)(dp + q*4);
        }
        if (c + 1 < cend) { CP_WAIT(1); } else { CP_WAIT(0); }
        __syncthreads();

        const uint32_t* Vb = Vs + (c & 1) * VS_WORDS;
#pragma unroll
        for (int ks = 0; ks < 8; ks++) {
            const uint32_t* pa = Ps + (wm2 + g)*PST + ks*8 + tg;
            uint32_t a0 = pa[0], a1 = pa[8*PST], a2 = pa[4], a3 = pa[8*PST + 4];
#pragma unroll
            for (int nt = 0; nt < 8; nt++) {
                const uint32_t* pb = Vb + (ks*8 + tg)*VSTRD + nt*8 + g;
                mma8(oacc[nt], a0, a1, a2, a3, pb[0], pb[4*VSTRD]);
            }
        }
        __syncthreads();
    }

    // masked region zeros: split 1 handles it
    if (split) {
        float4 z = make_float4(0.f, 0.f, 0.f, 0.f);
        for (int jc = nlive*64; jc < LQ; jc += 64) {
#pragma unroll
            for (int q = 0; q < 8; q++)
                *(float4*)&attn[rowbase + jc + q*4] = z;
        }
    }

#pragma unroll
    for (int nt = 0; nt < 8; nt++) {
        int d = nt*8 + 2*tg;
        int i = i0 + wm2 + g;
        *(float2*)&obuf[(size_t)i*DD + h*DHD + d] =
            make_float2(oacc[nt][0], oacc[nt][1]);
        *(float2*)&obuf[(size_t)(i+8)*DD + h*DHD + d] =
            make_float2(oacc[nt][2], oacc[nt][3]);
    }
}

// ---------------- partial-o sum (+ tf32 round for the Wo GEMM) ----------------
__global__ void oadd_kernel() {
    int idx = (blockIdx.x * 256 + threadIdx.x) * 4;
    float4 a = *(const float4*)&g_o[idx];
    float4 b = *(const float4*)&g_o2[idx];
    a.x = rnaf(a.x + b.x); a.y = rnaf(a.y + b.y);
    a.z = rnaf(a.z + b.z); a.w = rnaf(a.w + b.w);
    *(float4*)&g_o[idx] = a;
}

// ---------------- final: y = sigmoid(x@Wg+bg) * (yo1+yo2+bo) + x ----------------
__global__ void final_kernel(const float* __restrict__ x,
                             const float* __restrict__ bo,
                             const float* __restrict__ bg,
                             float* __restrict__ y) {
    int idx = blockIdx.x * 256 + threadIdx.x;
    int n = idx & (DD - 1);
    float yo = g_yo[idx] + g_yo2[idx] + bo[n];
    float gg = g_gg[idx] + bg[n];
    float gate = 1.f / (1.f + __expf(-gg));
    y[idx] = gate * yo + x[idx];
}

extern "C" void kernel_launch(void* const* d_in, const int* in_sizes, int n_in,
                              void* d_out, int out_size) {
    const float* x     = (const float*)d_in[0];
    const float* prev  = (const float*)d_in[1];
    const float* Wq    = (const float*)d_in[2];
    const float* Wk    = (const float*)d_in[3];
    const float* Wv    = (const float*)d_in[4];
    const float* Wo    = (const float*)d_in[5];
    const float* bo    = (const float*)d_in[6];
    const float* gamma = (const float*)d_in[7];
    const float* beta  = (const float*)d_in[8];
    const float* Wg    = (const float*)d_in[9];
    const float* bg    = (const float*)d_in[10];

    float* y    = (float*)d_out;
    float* attn = y + (size_t)LQ * DD;
    float* dots = attn + (size_t)NH * LQ * LQ;

    size_t gsmb = (size_t)GEMM_SMEM_WORDS * 4;
    cudaFuncSetAttribute(gemm_qkvg, cudaFuncAttributeMaxDynamicSharedMemorySize, (int)gsmb);
    cudaFuncSetAttribute(gemm_o,    cudaFuncAttributeMaxDynamicSharedMemorySize, (int)gsmb);
    size_t qsmb = (size_t)QK_SMEM_WORDS * 4;
    cudaFuncSetAttribute(qk_tf32, cudaFuncAttributeMaxDynamicSharedMemorySize, (int)qsmb);
    size_t avsmb = (size_t)AV_SMEM_WORDS * 4;
    cudaFuncSetAttribute(av_fused, cudaFuncAttributeMaxDynamicSharedMemorySize, (int)avsmb);

    prep_w<<<dim3(1024, 5), 256>>>(Wq, Wk, Wv, Wo, Wg);
    ln_kernel<<<LQ, 256>>>(x, gamma, beta);

    gemm_qkvg<<<dim3(8, 16, 4), 256, gsmb>>>();

    qk_masked<<<dim3(120, 16), 256>>>(prev, dots);
    qk_tf32<<<dim3(136, 1, 16), 256, qsmb>>>(prev, dots);
    sumk_kernel<<<(NH*LQ)/256, 256>>>();
    av_fused<<<dim3(32, 16), 256, avsmb>>>(dots, attn);
    oadd_kernel<<<(LQ*DD)/1024, 256>>>();

    gemm_o<<<dim3(8, 16, 2), 256, gsmb>>>();

    final_kernel<<<(LQ*DD)/256, 256>>>(x, bo, bg, y);
}